// round 11
// baseline (speedup 1.0000x reference)
#include <cuda_runtime.h>

#define BB 2
#define NN 16384
#define MM 4096
#define CC 32
#define KK 32

// float(0.01) — comparison threshold, frozen (bit-matches reference)
#define R2 0.00999999977648258209228515625f

#define GD 10
#define NCELL 1000
#define CAP 256
#define CELLCAP 64
#define MAXCELLS 64   // search window 0.2002 wide can span 4 cells/dim -> 4^3

// Scratch. g_cellcnt is zero at module load and restored to zero by
// group_kernel at the end of every kernel_launch call (self-restoring
// invariant -> no memset / zero kernel needed).
__device__ int    g_idx[BB * MM * KK];            // ball-query result [B][M][K]
__device__ float  g_feat_t[BB * NN * CC];         // transposed features [B][N][C]
__device__ float4 g_cell_pts[BB * NCELL * CELLCAP];
__device__ int    g_cellcnt[BB * NCELL];

// ---------------------------------------------------------------------------
__device__ __forceinline__ int cell_of(float x, float y, float z) {
    int cx = (int)(x * 10.f); cx = cx < 0 ? 0 : (cx > 9 ? 9 : cx);
    int cy = (int)(y * 10.f); cy = cy < 0 ? 0 : (cy > 9 ? 9 : cy);
    int cz = (int)(z * 10.f); cz = cz < 0 ? 0 : (cz > 9 ? 9 : cz);
    return (cx * GD + cy) * GD + cz;
}

// ---------------------------------------------------------------------------
// Fused binning + feature transpose.
// Blocks [0,32): bin points into padded per-cell lists (4 pts/thread, MLP-
// batched loads, gmem atomic slot grab). Blocks [32,1056): transpose feat
// [B][C][N] -> [B][N][C] in 32x32 tiles (hides the binning latency).
// ---------------------------------------------------------------------------
#define BIN_BLOCKS ((BB * NN) / (256 * 4))        // 32
__global__ __launch_bounds__(256) void bin_transpose_kernel(
    const float* __restrict__ pts,    // [B][3][N]
    const float* __restrict__ feat)   // [B][C][N]
{
    if (blockIdx.x < BIN_BLOCKS) {
        const int i0 = (blockIdx.x * 256 + threadIdx.x) * 4;
        const int b  = i0 >> 14;                  // / NN
        const int n0 = i0 & (NN - 1);
        const float* __restrict__ P = pts + b * 3 * NN;

        float x[4], y[4], z[4];
        #pragma unroll
        for (int j = 0; j < 4; ++j) {
            x[j] = __ldg(P + n0 + j);
            y[j] = __ldg(P + NN + n0 + j);
            z[j] = __ldg(P + 2 * NN + n0 + j);
        }
        #pragma unroll
        for (int j = 0; j < 4; ++j) {
            const int cell = b * NCELL + cell_of(x[j], y[j], z[j]);
            const int pos = atomicAdd(&g_cellcnt[cell], 1);
            if (pos < CELLCAP)
                g_cell_pts[(cell << 6) + pos] =
                    make_float4(x[j], y[j], z[j], __int_as_float(n0 + j));
        }
    } else {
        __shared__ float sm[32][33];
        const int t  = blockIdx.x - BIN_BLOCKS;   // 0..1023
        const int b  = t >> 9;
        const int n0 = (t & 511) * 32;
        const int tx = threadIdx.x & 31;
        const int ty = threadIdx.x >> 5;          // 0..7

        #pragma unroll
        for (int i = ty; i < 32; i += 8)
            sm[i][tx] = feat[(b * CC + i) * NN + n0 + tx];
        __syncthreads();
        #pragma unroll
        for (int i = ty; i < 32; i += 8)
            g_feat_t[(size_t)(b * NN + n0 + i) * CC + tx] = sm[tx][i];
    }
}

// ---------------------------------------------------------------------------
// Query: warp per center. Enumerate candidate cells (up to 4 per dim when the
// +/-0.1001 window straddles boundaries -> up to 64), prefetch cell counts
// warp-wide (2 lanes-worth), scan each cell's padded list; collect valid
// ORIGINAL indices, rank-select 32 smallest.
// Arithmetic bit-matches XLA lowering (FROZEN):
//   p2,c2: (x*x + y*y) + z*z  plain mul/add
//   dot:   fma(cz,pz, fma(cy,py, cx*px))
//   d2:    (c2 + p2) - 2*dot
// ---------------------------------------------------------------------------
#define QW 8
__global__ __launch_bounds__(256) void query_kernel(const float* __restrict__ ctr)
{
    __shared__ int buf[QW][CAP];
    __shared__ int sidx[QW][KK];
    __shared__ int scell[QW][MAXCELLS];

    const int w = threadIdx.x >> 5;
    const int lane = threadIdx.x & 31;
    const int gw = blockIdx.x * QW + w;           // 1024 blocks * 8 warps
    const int b = gw >> 12;                       // / MM
    const int m = gw & (MM - 1);

    const float cx = ctr[(b * 3 + 0) * MM + m];
    const float cy = ctr[(b * 3 + 1) * MM + m];
    const float cz = ctr[(b * 3 + 2) * MM + m];
    const float c2 = __fadd_rn(__fadd_rn(__fmul_rn(cx, cx), __fmul_rn(cy, cy)),
                               __fmul_rn(cz, cz));

    // conservative cell range (1e-4 margin swamps fp rounding)
    int lox = (int)((cx - 0.1001f) * 10.f); lox = lox < 0 ? 0 : lox;
    int hix = (int)((cx + 0.1001f) * 10.f); hix = hix > 9 ? 9 : hix;
    int loy = (int)((cy - 0.1001f) * 10.f); loy = loy < 0 ? 0 : loy;
    int hiy = (int)((cy + 0.1001f) * 10.f); hiy = hiy > 9 ? 9 : hiy;
    int loz = (int)((cz - 0.1001f) * 10.f); loz = loz < 0 ? 0 : loz;
    int hiz = (int)((cz + 0.1001f) * 10.f); hiz = hiz > 9 ? 9 : hiz;

    // enumerate candidate cells (identical across lanes; lane0 records)
    int cn = 0;
    for (int xi = lox; xi <= hix; ++xi)
        for (int yi = loy; yi <= hiy; ++yi)
            for (int zi = loz; zi <= hiz; ++zi) {
                if (lane == 0) scell[w][cn] = (xi * GD + yi) * GD + zi;
                ++cn;
            }
    __syncwarp();

    // warp-wide prefetch of cell counts (two lanes-worth covers MAXCELLS=64)
    int myc0 = (lane < cn)      ? g_cellcnt[b * NCELL + scell[w][lane]]      : 0;
    int myc1 = (lane + 32 < cn) ? g_cellcnt[b * NCELL + scell[w][lane + 32]] : 0;

    const float4* __restrict__ pp = g_cell_pts + ((size_t)b * NCELL << 6);

    int cnt = 0;
    for (int j = 0; j < cn; ++j) {
        const int cell = scell[w][j];
        int ccnt = __shfl_sync(0xffffffffu, (j < 32) ? myc0 : myc1, j & 31);
        ccnt = ccnt < CELLCAP ? ccnt : CELLCAP;
        const float4* __restrict__ row = pp + ((size_t)cell << 6);
        for (int t = lane; t - lane < ccnt; t += 32) {
            const bool inb = t < ccnt;
            float4 q;
            if (inb) q = row[t];
            else     q = make_float4(1e9f, 1e9f, 1e9f, 0.f);
            const float p2 = __fadd_rn(__fadd_rn(__fmul_rn(q.x, q.x), __fmul_rn(q.y, q.y)),
                                       __fmul_rn(q.z, q.z));
            const float dot = __fmaf_rn(cz, q.z, __fmaf_rn(cy, q.y, __fmul_rn(cx, q.x)));
            const float d2 = __fadd_rn(__fadd_rn(c2, p2), __fmul_rn(-2.0f, dot));
            const bool valid = inb && (d2 < R2);
            const unsigned mask = __ballot_sync(0xffffffffu, valid);
            if (valid) {
                const int pos = cnt + __popc(mask & ((1u << lane) - 1u));
                if (pos < CAP) buf[w][pos] = __float_as_int(q.w);
            }
            cnt += __popc(mask);
        }
    }
    __syncwarp();

    // Rank-select 32 smallest indices (unique values -> ranks unique)
    const int cc = cnt < CAP ? cnt : CAP;
    const int IMAX = 0x7fffffff;
    const int v0 = (lane      < cc) ? buf[w][lane]      : IMAX;
    const int v1 = (lane + 32 < cc) ? buf[w][lane + 32] : IMAX;
    const int v2 = (lane + 64 < cc) ? buf[w][lane + 64] : IMAX;
    const int v3 = (lane + 96 < cc) ? buf[w][lane + 96] : IMAX;
    int r0 = 0, r1 = 0, r2 = 0, r3 = 0;
    for (int g = 0; g < cc; ++g) {
        const int u = buf[w][g];                  // broadcast read
        r0 += (u < v0); r1 += (u < v1); r2 += (u < v2); r3 += (u < v3);
    }
    if (lane      < cc && r0 < KK) sidx[w][r0] = v0;
    if (lane + 32 < cc && r1 < KK) sidx[w][r1] = v1;
    if (lane + 64 < cc && r2 < KK) sidx[w][r2] = v2;
    if (lane + 96 < cc && r3 < KK) sidx[w][r3] = v3;
    // rare overflow path (cc in (128,256])
    for (int j = 128 + lane; j < cc; j += 32) {
        const int vv = buf[w][j];
        int r = 0;
        for (int g = 0; g < cc; ++g) r += (buf[w][g] < vv);
        if (r < KK) sidx[w][r] = vv;
    }
    __syncwarp();

    int outv;
    if (cnt == 0) {
        outv = 0;
    } else {
        const int first = sidx[w][0];
        outv = (lane < cnt) ? sidx[w][lane] : first;
    }
    g_idx[(b * MM + m) * KK + lane] = outv;
}

// ---------------------------------------------------------------------------
// Unified grouping: grid (M/32, 5, B), 256 threads.
// y in [0,4): feature plane kc=y — warp w owns k=kc*8+w; MLP-batched 128B row
//             gathers from g_feat_t staged through a padded smem tile.
// y == 4   : coords — warp w owns k in [4w, 4w+4); per-lane m; scattered 4B
//            gathers (L1-hot, 64KB src), coalesced-over-m stores. These
//            blocks also restore g_cellcnt to zero for the next call.
// ---------------------------------------------------------------------------
__global__ __launch_bounds__(256) void group_kernel(
    const float* __restrict__ pts,    // [B][3][N]
    const float* __restrict__ ctr,    // [B][3][M]
    float* __restrict__ out)          // [B][35][K][M]
{
    const int tid  = threadIdx.x;
    const int w    = tid >> 5;
    const int lane = tid & 31;
    const int m0 = blockIdx.x * 32;
    const int b  = blockIdx.z;

    if (blockIdx.y < 4) {
        __shared__ int   sidx2[32 * 8];          // [m][kk]
        __shared__ float tile[32 * 257];         // [c][w*32+m], padded
        const int kc = blockIdx.y;

        {
            const int ml = tid >> 3, kk = tid & 7;
            sidx2[ml * 8 + kk] = g_idx[(b * MM + m0 + ml) * KK + kc * 8 + kk];
        }
        __syncthreads();

        const float* __restrict__ ft = g_feat_t + (size_t)b * NN * CC + lane;

        int idxs[32];
        #pragma unroll
        for (int m = 0; m < 32; ++m) idxs[m] = sidx2[m * 8 + w];

        #pragma unroll
        for (int mb = 0; mb < 4; ++mb) {
            float v[8];
            #pragma unroll
            for (int j = 0; j < 8; ++j)
                v[j] = __ldg(ft + (size_t)idxs[mb * 8 + j] * CC);
            #pragma unroll
            for (int j = 0; j < 8; ++j)
                tile[lane * 257 + w * 32 + mb * 8 + j] = v[j];
        }
        __syncthreads();

        #pragma unroll
        for (int i = 0; i < 32; ++i) {
            out[(size_t)((b * 35 + 3 + i) * KK + kc * 8 + w) * MM + m0 + lane] =
                tile[i * 257 + w * 32 + lane];
        }
    } else {
        __shared__ int sidxc[32 * 33];           // [m][k] padded

        for (int t = tid; t < 32 * KK; t += 256) {
            const int ml = t >> 5, k = t & 31;
            sidxc[ml * 33 + k] = g_idx[(b * MM + m0 + ml) * KK + k];
        }
        __syncthreads();

        int idx4[4];
        #pragma unroll
        for (int j = 0; j < 4; ++j) idx4[j] = sidxc[lane * 33 + w * 4 + j];

        #pragma unroll
        for (int c = 0; c < 3; ++c) {
            const float* __restrict__ src = pts + (b * 3 + c) * NN;
            const float sub = ctr[(b * 3 + c) * MM + m0 + lane];
            float v[4];
            #pragma unroll
            for (int j = 0; j < 4; ++j) v[j] = __ldg(src + idx4[j]);
            #pragma unroll
            for (int j = 0; j < 4; ++j)
                out[(size_t)((b * 35 + c) * KK + w * 4 + j) * MM + m0 + lane] =
                    __fadd_rn(v[j], -sub);
        }

        // Restore g_cellcnt = 0 for the next kernel_launch call.
        // 256 cleanup blocks (b*128 + x), 2000 counters -> 8 per block.
        const int cb = (b << 7) + blockIdx.x;    // 0..255
        if (tid < 8) {
            const int ci = cb * 8 + tid;
            if (ci < BB * NCELL) g_cellcnt[ci] = 0;
        }
    }
}

extern "C" void kernel_launch(void* const* d_in, const int* in_sizes, int n_in,
                              void* d_out, int out_size)
{
    const float* pts  = (const float*)d_in[0];   // [B][3][N]
    const float* ctr  = (const float*)d_in[1];   // [B][3][M]
    const float* feat = (const float*)d_in[2];   // [B][C][N]
    float* out = (float*)d_out;

    bin_transpose_kernel<<<BIN_BLOCKS + BB * (NN / 32), 256>>>(pts, feat);

    query_kernel<<<BB * MM / QW, 256>>>(ctr);

    {
        dim3 grid(MM / 32, 5, BB);
        group_kernel<<<grid, 256>>>(pts, ctr, out);
    }
}

// round 12
// speedup vs baseline: 1.6496x; 1.6496x over previous
#include <cuda_runtime.h>

#define BB 2
#define NN 16384
#define MM 4096
#define CC 32
#define KK 32

// float(0.01) — comparison threshold, frozen (bit-matches reference)
#define R2 0.00999999977648258209228515625f

#define GD 10
#define NCELL 1000
#define CAP 256

// Scratch. g_cellcur is zero at module load and restored to zero by
// group_kernel at the end of every kernel_launch call (self-restoring
// invariant -> no zero kernel needed).
__device__ int    g_idx[BB * MM * KK];        // ball-query result [B][M][K]
__device__ float  g_feat_t[BB * NN * CC];     // transposed features [B][N][C]
__device__ float4 g_pts4[BB * NN];            // cell-sorted (x,y,z,idx-bits)
__device__ int    g_cellcur[BB * NCELL];      // counts -> scatter cursors
__device__ int    g_cellstart[BB * (NCELL + 1)];

// ---------------------------------------------------------------------------
__device__ __forceinline__ int cell_of(float x, float y, float z) {
    int cx = (int)(x * 10.f); cx = cx < 0 ? 0 : (cx > 9 ? 9 : cx);
    int cy = (int)(y * 10.f); cy = cy < 0 ? 0 : (cy > 9 ? 9 : cy);
    int cz = (int)(z * 10.f); cz = cz < 0 ? 0 : (cz > 9 ? 9 : cz);
    return (cx * GD + cy) * GD + cz;
}

// ---------------------------------------------------------------------------
// Fused count + feature transpose. Blocks [0,128): histogram points into
// cells (global atomics). Blocks [128,1152): transpose feat [B][C][N] ->
// [B][N][C] in 32x32 tiles. Independent arrays -> no ordering hazard; the
// transpose work hides the count blocks' atomic latency.
// ---------------------------------------------------------------------------
__global__ __launch_bounds__(256) void count_transpose_kernel(
    const float* __restrict__ pts,    // [B][3][N]
    const float* __restrict__ feat)   // [B][C][N]
{
    if (blockIdx.x < (BB * NN) / 256) {
        const int i = blockIdx.x * 256 + threadIdx.x;
        const int b = i >> 14;                    // / NN
        const int n = i & (NN - 1);
        const float* __restrict__ P = pts + b * 3 * NN;
        atomicAdd(&g_cellcur[b * NCELL + cell_of(P[n], P[NN + n], P[2 * NN + n])], 1);
    } else {
        __shared__ float sm[32][33];
        const int t  = blockIdx.x - (BB * NN) / 256;   // 0..1023
        const int b  = t >> 9;
        const int n0 = (t & 511) * 32;
        const int tx = threadIdx.x & 31;
        const int ty = threadIdx.x >> 5;               // 0..7

        #pragma unroll
        for (int i = ty; i < 32; i += 8)
            sm[i][tx] = feat[(b * CC + i) * NN + n0 + tx];
        __syncthreads();
        #pragma unroll
        for (int i = ty; i < 32; i += 8)
            g_feat_t[(size_t)(b * NN + n0 + i) * CC + tx] = sm[tx][i];
    }
}

// grid = BB blocks, 1024 threads: exclusive scan of 1000 counts per batch
__global__ __launch_bounds__(1024) void prefix_kernel() {
    __shared__ int s[1024];
    const int b = blockIdx.x, tid = threadIdx.x;
    const int v = (tid < NCELL) ? g_cellcur[b * NCELL + tid] : 0;
    s[tid] = v;
    __syncthreads();
    #pragma unroll
    for (int off = 1; off < 1024; off <<= 1) {
        const int t = (tid >= off) ? s[tid - off] : 0;
        __syncthreads();
        s[tid] += t;
        __syncthreads();
    }
    const int excl = s[tid] - v;
    if (tid < NCELL) {
        g_cellstart[b * (NCELL + 1) + tid] = excl;
        g_cellcur[b * NCELL + tid] = excl;       // scatter cursor
    }
    if (tid == NCELL - 1) g_cellstart[b * (NCELL + 1) + NCELL] = s[tid];
}

// 2 points per thread, loads batched upfront -> 2 independent atomic+store
// chains in flight per thread (halves exposed ATOMG latency).
__global__ __launch_bounds__(256) void scatter_kernel(const float* __restrict__ pts) {
    const int i0 = (blockIdx.x * 256 + threadIdx.x) * 2;
    const int b  = i0 >> 14;                     // pairs never straddle batches
    const int n0 = i0 & (NN - 1);
    const float* __restrict__ P = pts + b * 3 * NN;

    float x[2], y[2], z[2];
    #pragma unroll
    for (int j = 0; j < 2; ++j) {
        x[j] = __ldg(P + n0 + j);
        y[j] = __ldg(P + NN + n0 + j);
        z[j] = __ldg(P + 2 * NN + n0 + j);
    }
    #pragma unroll
    for (int j = 0; j < 2; ++j) {
        const int pos = atomicAdd(&g_cellcur[b * NCELL + cell_of(x[j], y[j], z[j])], 1);
        g_pts4[b * NN + pos] = make_float4(x[j], y[j], z[j], __int_as_float(n0 + j));
    }
}

// ---------------------------------------------------------------------------
// Query: warp per center. Scan 27-neighborhood as contiguous z-strips of the
// cell-sorted array; collect valid ORIGINAL indices, rank-select 32 smallest.
// Arithmetic bit-matches XLA lowering (FROZEN):
//   p2,c2: (x*x + y*y) + z*z  plain mul/add
//   dot:   fma(cz,pz, fma(cy,py, cx*px))
//   d2:    (c2 + p2) - 2*dot
// ---------------------------------------------------------------------------
#define QW 8
__global__ __launch_bounds__(256) void query_kernel(const float* __restrict__ ctr)
{
    __shared__ int buf[QW][CAP];
    __shared__ int sidx[QW][KK];

    const int w = threadIdx.x >> 5;
    const int lane = threadIdx.x & 31;
    const int gw = blockIdx.x * QW + w;           // 1024 blocks * 8 warps
    const int b = gw >> 12;                       // / MM
    const int m = gw & (MM - 1);

    const float cx = ctr[(b * 3 + 0) * MM + m];
    const float cy = ctr[(b * 3 + 1) * MM + m];
    const float cz = ctr[(b * 3 + 2) * MM + m];
    const float c2 = __fadd_rn(__fadd_rn(__fmul_rn(cx, cx), __fmul_rn(cy, cy)),
                               __fmul_rn(cz, cz));

    // conservative cell range (1e-4 margin swamps fp rounding)
    int lox = (int)((cx - 0.1001f) * 10.f); lox = lox < 0 ? 0 : lox;
    int hix = (int)((cx + 0.1001f) * 10.f); hix = hix > 9 ? 9 : hix;
    int loy = (int)((cy - 0.1001f) * 10.f); loy = loy < 0 ? 0 : loy;
    int hiy = (int)((cy + 0.1001f) * 10.f); hiy = hiy > 9 ? 9 : hiy;
    int loz = (int)((cz - 0.1001f) * 10.f); loz = loz < 0 ? 0 : loz;
    int hiz = (int)((cz + 0.1001f) * 10.f); hiz = hiz > 9 ? 9 : hiz;

    const int* __restrict__ cs = g_cellstart + b * (NCELL + 1);
    const float4* __restrict__ pp = g_pts4 + b * NN;

    int cnt = 0;
    for (int xi = lox; xi <= hix; ++xi) {
        for (int yi = loy; yi <= hiy; ++yi) {
            const int base = (xi * GD + yi) * GD;
            const int s = cs[base + loz];
            const int e = cs[base + hiz + 1];
            for (int t = s + lane; t - lane < e; t += 32) {
                const bool inb = t < e;
                float4 q;
                if (inb) q = pp[t];
                else     q = make_float4(1e9f, 1e9f, 1e9f, 0.f);
                const float p2 = __fadd_rn(__fadd_rn(__fmul_rn(q.x, q.x), __fmul_rn(q.y, q.y)),
                                           __fmul_rn(q.z, q.z));
                const float dot = __fmaf_rn(cz, q.z, __fmaf_rn(cy, q.y, __fmul_rn(cx, q.x)));
                const float d2 = __fadd_rn(__fadd_rn(c2, p2), __fmul_rn(-2.0f, dot));
                const bool valid = inb && (d2 < R2);
                const unsigned mask = __ballot_sync(0xffffffffu, valid);
                if (valid) {
                    const int pos = cnt + __popc(mask & ((1u << lane) - 1u));
                    if (pos < CAP) buf[w][pos] = __float_as_int(q.w);
                }
                cnt += __popc(mask);
            }
        }
    }
    __syncwarp();

    // Rank-select 32 smallest indices (unique values -> ranks unique)
    const int cc = cnt < CAP ? cnt : CAP;
    const int IMAX = 0x7fffffff;
    const int v0 = (lane      < cc) ? buf[w][lane]      : IMAX;
    const int v1 = (lane + 32 < cc) ? buf[w][lane + 32] : IMAX;
    const int v2 = (lane + 64 < cc) ? buf[w][lane + 64] : IMAX;
    const int v3 = (lane + 96 < cc) ? buf[w][lane + 96] : IMAX;
    int r0 = 0, r1 = 0, r2 = 0, r3 = 0;
    for (int g = 0; g < cc; ++g) {
        const int u = buf[w][g];                  // broadcast read
        r0 += (u < v0); r1 += (u < v1); r2 += (u < v2); r3 += (u < v3);
    }
    if (lane      < cc && r0 < KK) sidx[w][r0] = v0;
    if (lane + 32 < cc && r1 < KK) sidx[w][r1] = v1;
    if (lane + 64 < cc && r2 < KK) sidx[w][r2] = v2;
    if (lane + 96 < cc && r3 < KK) sidx[w][r3] = v3;
    // rare overflow path (cc in (128,256])
    for (int j = 128 + lane; j < cc; j += 32) {
        const int vv = buf[w][j];
        int r = 0;
        for (int g = 0; g < cc; ++g) r += (buf[w][g] < vv);
        if (r < KK) sidx[w][r] = vv;
    }
    __syncwarp();

    int outv;
    if (cnt == 0) {
        outv = 0;
    } else {
        const int first = sidx[w][0];
        outv = (lane < cnt) ? sidx[w][lane] : first;
    }
    g_idx[(b * MM + m) * KK + lane] = outv;
}

// ---------------------------------------------------------------------------
// Unified grouping: grid (M/32, 5, B), 256 threads.
// y in [0,4): feature plane kc=y — warp w owns k=kc*8+w; MLP-batched 128B row
//             gathers from g_feat_t staged through a padded smem tile.
// y == 4   : coords — warp w owns k in [4w, 4w+4); per-lane m; scattered 4B
//            gathers (L1-hot, 64KB src), coalesced-over-m stores. These
//            blocks also restore g_cellcur to zero for the next call.
// ---------------------------------------------------------------------------
__global__ __launch_bounds__(256) void group_kernel(
    const float* __restrict__ pts,    // [B][3][N]
    const float* __restrict__ ctr,    // [B][3][M]
    float* __restrict__ out)          // [B][35][K][M]
{
    const int tid  = threadIdx.x;
    const int w    = tid >> 5;
    const int lane = tid & 31;
    const int m0 = blockIdx.x * 32;
    const int b  = blockIdx.z;

    if (blockIdx.y < 4) {
        __shared__ int   sidx2[32 * 8];          // [m][kk]
        __shared__ float tile[32 * 257];         // [c][w*32+m], padded
        const int kc = blockIdx.y;

        {
            const int ml = tid >> 3, kk = tid & 7;
            sidx2[ml * 8 + kk] = g_idx[(b * MM + m0 + ml) * KK + kc * 8 + kk];
        }
        __syncthreads();

        const float* __restrict__ ft = g_feat_t + (size_t)b * NN * CC + lane;

        int idxs[32];
        #pragma unroll
        for (int m = 0; m < 32; ++m) idxs[m] = sidx2[m * 8 + w];

        #pragma unroll
        for (int mb = 0; mb < 4; ++mb) {
            float v[8];
            #pragma unroll
            for (int j = 0; j < 8; ++j)
                v[j] = __ldg(ft + (size_t)idxs[mb * 8 + j] * CC);
            #pragma unroll
            for (int j = 0; j < 8; ++j)
                tile[lane * 257 + w * 32 + mb * 8 + j] = v[j];
        }
        __syncthreads();

        #pragma unroll
        for (int i = 0; i < 32; ++i) {
            out[(size_t)((b * 35 + 3 + i) * KK + kc * 8 + w) * MM + m0 + lane] =
                tile[i * 257 + w * 32 + lane];
        }
    } else {
        __shared__ int sidxc[32 * 33];           // [m][k] padded

        for (int t = tid; t < 32 * KK; t += 256) {
            const int ml = t >> 5, k = t & 31;
            sidxc[ml * 33 + k] = g_idx[(b * MM + m0 + ml) * KK + k];
        }
        __syncthreads();

        int idx4[4];
        #pragma unroll
        for (int j = 0; j < 4; ++j) idx4[j] = sidxc[lane * 33 + w * 4 + j];

        #pragma unroll
        for (int c = 0; c < 3; ++c) {
            const float* __restrict__ src = pts + (b * 3 + c) * NN;
            const float sub = ctr[(b * 3 + c) * MM + m0 + lane];
            float v[4];
            #pragma unroll
            for (int j = 0; j < 4; ++j) v[j] = __ldg(src + idx4[j]);
            #pragma unroll
            for (int j = 0; j < 4; ++j)
                out[(size_t)((b * 35 + c) * KK + w * 4 + j) * MM + m0 + lane] =
                    __fadd_rn(v[j], -sub);
        }

        // Restore g_cellcur = 0 for the next kernel_launch call.
        // 256 cleanup blocks (b*128 + x), 2000 counters -> 8 per block.
        const int cb = (b << 7) + blockIdx.x;    // 0..255
        if (tid < 8) {
            const int ci = cb * 8 + tid;
            if (ci < BB * NCELL) g_cellcur[ci] = 0;
        }
    }
}

extern "C" void kernel_launch(void* const* d_in, const int* in_sizes, int n_in,
                              void* d_out, int out_size)
{
    const float* pts  = (const float*)d_in[0];   // [B][3][N]
    const float* ctr  = (const float*)d_in[1];   // [B][3][M]
    const float* feat = (const float*)d_in[2];   // [B][C][N]
    float* out = (float*)d_out;

    count_transpose_kernel<<<(BB * NN) / 256 + BB * (NN / 32), 256>>>(pts, feat);
    prefix_kernel<<<BB, 1024>>>();
    scatter_kernel<<<(BB * NN) / (256 * 2), 256>>>(pts);
    query_kernel<<<BB * MM / QW, 256>>>(ctr);

    {
        dim3 grid(MM / 32, 5, BB);
        group_kernel<<<grid, 256>>>(pts, ctr, out);
    }
}